// round 11
// baseline (speedup 1.0000x reference)
#include <cuda_runtime.h>
#include <cstdint>

// ---------------------------------------------------------------------------
// ManifoldHyperConnection fused kernel, GB300 (sm_103a) — round 11
//
// out[m,c] = sum_n G[m,n] * x[n,c], G folded from sigmoid/Cayley of 24 dots.
//
// Dot-phase mapping REWORKED to cut L1 broadcast writeback (~5.3 -> 2.7 B/MAC):
//   lane = token (tau=2: lane owns tokens l and l+32)
//   warp = (row-group of 6 rows) x (channel half)   [8 warps]
//   x:  distinct LDS.128 per lane (writeback fully useful)
//   w:  uniform (broadcast) LDG.128, amortized over 2 tokens/lane
//   acc: 12 x u64 packed f32x2 per thread (row x token), full lane use
//
// Block: 64 tokens, 256 thr, grid 256, 3 CTAs/SM. Chunks of 64 channels,
// cp.async double-buffered. Epilogue Cayley -> G; phase 3 applies G (L2-hot).
// ---------------------------------------------------------------------------

typedef unsigned long long u64;

__device__ __forceinline__ u64 fma2(u64 a, u64 b, u64 c) {
    u64 d;
    asm("fma.rn.f32x2 %0, %1, %2, %3;" : "=l"(d) : "l"(a), "l"(b), "l"(c));
    return d;
}
__device__ __forceinline__ u64 pk2(float lo, float hi) {
    u64 r;
    asm("mov.b64 %0, {%1, %2};" : "=l"(r) : "f"(lo), "f"(hi));
    return r;
}
__device__ __forceinline__ void upk2(u64 v, float& lo, float& hi) {
    asm("mov.b64 {%0, %1}, %2;" : "=f"(lo), "=f"(hi) : "l"(v));
}

// weights: wB[j4][row]  (float4 = rows' 4 channels), 1024*24 float4 = 384 KB
static __device__ float4 g_WB[1024 * 24];

// ---------------------------------------------------------------------------
// prep: g_WB[j4*24 + r] = alpha_r * norm_w[j] * W_r[j],  j = j4*4 + c
// ---------------------------------------------------------------------------
__global__ void mhc_prep_kernel(const float* __restrict__ norm_w,
                                const float* __restrict__ W_pre,
                                const float* __restrict__ W_post,
                                const float* __restrict__ W_res,
                                const float* __restrict__ a_pre,
                                const float* __restrict__ a_post,
                                const float* __restrict__ a_res) {
    int idx = blockIdx.x * 256 + threadIdx.x;
    if (idx >= 1024 * 24) return;
    int j4 = idx / 24;
    int r  = idx - j4 * 24;
    float alpha;
    const float* Wrow;
    if (r < 4)       { alpha = a_pre[0];  Wrow = W_pre  + r * 4096; }
    else if (r < 8)  { alpha = a_post[0]; Wrow = W_post + (r - 4) * 4096; }
    else             { alpha = a_res[0];  Wrow = W_res  + (r - 8) * 4096; }
    int j = j4 * 4;
    float4 v;
    v.x = alpha * Wrow[j + 0] * norm_w[j + 0];
    v.y = alpha * Wrow[j + 1] * norm_w[j + 1];
    v.z = alpha * Wrow[j + 2] * norm_w[j + 2];
    v.w = alpha * Wrow[j + 3] * norm_w[j + 3];
    g_WB[idx] = v;
}

// Tile/loop config
#define TB       64      // tokens per block
#define NCHUNK   64      // chunks of 64 channels
#define CF4      16      // float4 per token per chunk
#define ROWB     272     // bytes per token row in buffer (256 + 16 pad)
#define BUFB     17408   // 64 * 272

// smem layout (bytes)
#define SMEM_SX    0          // 2 buffers                        34816
#define SMEM_DOTS  34816      // float dots2[2][64][24]           12288
#define SMEM_SSQ   47104      // float ssqs[2][64]                  512
#define SMEM_SG    47616      // float sG[64][16]                  4096
#define SMEM_TOTAL 51712

__device__ __forceinline__ void load_chunk(uint32_t sbase, const float4* x4g,
                                           size_t tok0, int cc, int tid) {
    const int buf = cc & 1;
#pragma unroll
    for (int i = 0; i < 4; i++) {
        int idx = i * 256 + tid;        // == tt*16 + c4
        int tt  = idx >> 4;
        int c4  = idx & 15;
        const float4* src = x4g + ((tok0 + tt) * 1024 + cc * CF4 + c4);
        uint32_t dst = sbase + buf * BUFB + tt * ROWB + c4 * 16;
        asm volatile("cp.async.cg.shared.global [%0], [%1], 16;"
                     :: "r"(dst), "l"(src));
    }
    asm volatile("cp.async.commit_group;");
}

__global__ void __launch_bounds__(256, 3)
mhc_main_kernel(const float* __restrict__ x,
                const float* __restrict__ b_pre,
                const float* __restrict__ b_post,
                const float* __restrict__ b_res,
                float* __restrict__ out) {
    extern __shared__ char smem[];
    float* dots2 = (float*)(smem + SMEM_DOTS);  // [2][64][24]
    float* ssqs  = (float*)(smem + SMEM_SSQ);   // [2][64]
    float* sG    = (float*)(smem + SMEM_SG);    // [64][16]

    const int tid  = threadIdx.x;
    const int w    = tid >> 5;
    const int lane = tid & 31;
    const int rg   = w & 3;   // row-group: rows 6*rg .. 6*rg+5
    const int h    = w >> 2;  // channel half
    const size_t tok0 = (size_t)blockIdx.x * TB;

    const float4*     x4g = (const float4*)x;
    const ulonglong2* xg2 = (const ulonglong2*)x;
    const ulonglong2* wB2 = (const ulonglong2*)g_WB;

    const uint32_t sbase = (uint32_t)__cvta_generic_to_shared(smem);

    u64 acc[12];
#pragma unroll
    for (int i = 0; i < 12; i++) acc[i] = 0ull;
    float sq0 = 0.0f, sq1 = 0.0f;  // rg==0 warps: ssq for tokens lane, lane+32

    // ------------------ Phase 1: double-buffered chunk loop -----------------
    load_chunk(sbase, x4g, tok0, 0, tid);

    for (int cc = 0; cc < NCHUNK; cc++) {
        if (cc < NCHUNK - 1) {
            load_chunk(sbase, x4g, tok0, cc + 1, tid);
            asm volatile("cp.async.wait_group 1;");
        } else {
            asm volatile("cp.async.wait_group 0;");
        }
        __syncthreads();

        const int buf = cc & 1;
        // x for lane's tokens, this warp's channel half (8 f4 per chunk)
        const char* xb0 = smem + buf * BUFB + lane * ROWB + h * 128;
        const char* xb1 = xb0 + 32 * ROWB;
        // weights for this warp: rows rg*6.., j4 = cc*16 + h*8 + m
        const ulonglong2* wrow = wB2 + ((size_t)(cc * 16 + h * 8) * 24 + rg * 6);

#pragma unroll
        for (int m = 0; m < 8; m++) {
            ulonglong2 xv0 = *(const ulonglong2*)(xb0 + m * 16);
            ulonglong2 xv1 = *(const ulonglong2*)(xb1 + m * 16);
            if (rg == 0) {
                float a, b;
                upk2(xv0.x, a, b); sq0 = fmaf(a, a, sq0); sq0 = fmaf(b, b, sq0);
                upk2(xv0.y, a, b); sq0 = fmaf(a, a, sq0); sq0 = fmaf(b, b, sq0);
                upk2(xv1.x, a, b); sq1 = fmaf(a, a, sq1); sq1 = fmaf(b, b, sq1);
                upk2(xv1.y, a, b); sq1 = fmaf(a, a, sq1); sq1 = fmaf(b, b, sq1);
            }
#pragma unroll
            for (int r = 0; r < 6; r++) {
                ulonglong2 wv = wrow[m * 24 + r];  // uniform LDG.128
                acc[r * 2 + 0] = fma2(wv.x, xv0.x, acc[r * 2 + 0]);
                acc[r * 2 + 0] = fma2(wv.y, xv0.y, acc[r * 2 + 0]);
                acc[r * 2 + 1] = fma2(wv.x, xv1.x, acc[r * 2 + 1]);
                acc[r * 2 + 1] = fma2(wv.y, xv1.y, acc[r * 2 + 1]);
            }
        }
        __syncthreads();  // all reads of this buffer done before reuse
    }

    // ------------------ Phase 2: write partial dots, reduce, Cayley ---------
#pragma unroll
    for (int r = 0; r < 6; r++) {
#pragma unroll
        for (int ti = 0; ti < 2; ti++) {
            float lo, hi;
            upk2(acc[r * 2 + ti], lo, hi);
            int t = lane + ti * 32;
            dots2[(h * TB + t) * 24 + rg * 6 + r] = lo + hi;
        }
    }
    if (rg == 0) {
        ssqs[h * TB + lane]      = sq0;
        ssqs[h * TB + lane + 32] = sq1;
    }
    __syncthreads();

    if (tid < TB) {
        const int t = tid;
        float ssq = ssqs[t] + ssqs[TB + t];
        float rinv = rsqrtf(ssq * (1.0f / 4096.0f) + 1e-6f);
        float d[24];
#pragma unroll
        for (int k = 0; k < 24; k++)
            d[k] = (dots2[t * 24 + k] + dots2[(TB + t) * 24 + k]) * rinv;

        float Hpre[4], Hpost[4];
#pragma unroll
        for (int i = 0; i < 4; i++) {
            Hpre[i]  = 1.0f / (1.0f + expf(-(d[i]     + b_pre[i])));
            Hpost[i] = 2.0f / (1.0f + expf(-(d[4 + i] + b_post[i])));
        }
        // Cayley: A = I - S, Bq = I + S, S = 0.5 (M - M^T)
        float A[4][4], Bq[4][4];
#pragma unroll
        for (int a = 0; a < 4; a++)
#pragma unroll
            for (int b = 0; b < 4; b++) {
                float Mab = d[8 + a * 4 + b] + b_res[a * 4 + b];
                float Mba = d[8 + b * 4 + a] + b_res[b * 4 + a];
                float S   = 0.5f * (Mab - Mba);
                float id  = (a == b) ? 1.0f : 0.0f;
                A[a][b]  = id - S;
                Bq[a][b] = id + S;
            }
#pragma unroll
        for (int r = 0; r < 4; r++) {
            float inv = 1.0f / A[r][r];
#pragma unroll
            for (int c = 0; c < 4; c++) { A[r][c] *= inv; Bq[r][c] *= inv; }
#pragma unroll
            for (int rr = 0; rr < 4; rr++) {
                if (rr == r) continue;
                float f = A[rr][r];
#pragma unroll
                for (int c = 0; c < 4; c++) {
                    A[rr][c]  -= f * A[r][c];
                    Bq[rr][c] -= f * Bq[r][c];
                }
            }
        }
#pragma unroll
        for (int m = 0; m < 4; m++)
#pragma unroll
            for (int n = 0; n < 4; n++)
                sG[t * 16 + m * 4 + n] = Bq[m][n] + Hpost[m] * Hpre[n];
    }
    __syncthreads();

    // ------------------ Phase 3: out = G @ x (per token, L2-hot x) ----------
    ulonglong2* og2 = (ulonglong2*)out;
    for (int it = 0; it < TB; it++) {
        u64 g2a[16];
#pragma unroll
        for (int q = 0; q < 16; q++) {
            float gv = sG[it * 16 + q];
            g2a[q] = pk2(gv, gv);
        }
        u64 xl[4], xh[4];
#pragma unroll
        for (int n = 0; n < 4; n++) {
            ulonglong2 v = xg2[(tok0 + it) * 1024 + n * 256 + tid];
            xl[n] = v.x;
            xh[n] = v.y;
        }
#pragma unroll
        for (int m = 0; m < 4; m++) {
            u64 al = 0ull, ah = 0ull;
#pragma unroll
            for (int n = 0; n < 4; n++) {
                al = fma2(g2a[m * 4 + n], xl[n], al);
                ah = fma2(g2a[m * 4 + n], xh[n], ah);
            }
            ulonglong2 o;
            o.x = al;
            o.y = ah;
            og2[(tok0 + it) * 1024 + m * 256 + tid] = o;
        }
    }
}

extern "C" void kernel_launch(void* const* d_in, const int* in_sizes, int n_in,
                              void* d_out, int out_size) {
    const float* x      = (const float*)d_in[0];
    const float* norm_w = (const float*)d_in[1];
    const float* W_pre  = (const float*)d_in[2];
    const float* W_post = (const float*)d_in[3];
    const float* W_res  = (const float*)d_in[4];
    const float* b_pre  = (const float*)d_in[5];
    const float* b_post = (const float*)d_in[6];
    const float* b_res  = (const float*)d_in[7];
    const float* a_pre  = (const float*)d_in[8];
    const float* a_post = (const float*)d_in[9];
    const float* a_res  = (const float*)d_in[10];
    float* out = (float*)d_out;

    const int BL   = in_sizes[0] / 4096;  // 16384 tokens
    const int nblk = BL / TB;             // 256 blocks

    cudaFuncSetAttribute(mhc_main_kernel,
                         cudaFuncAttributeMaxDynamicSharedMemorySize,
                         SMEM_TOTAL);

    mhc_prep_kernel<<<96, 256>>>(norm_w, W_pre, W_post, W_res,
                                 a_pre, a_post, a_res);
    mhc_main_kernel<<<nblk, 256, SMEM_TOTAL>>>(x, b_pre, b_post, b_res, out);
}

// round 12
// speedup vs baseline: 1.6645x; 1.6645x over previous
#include <cuda_runtime.h>
#include <cstdint>

// ---------------------------------------------------------------------------
// ManifoldHyperConnection fused kernel, GB300 (sm_103a) — round 12
//
// out[m,c] = sum_n G[m,n] * x[n,c], G folded from sigmoid/Cayley of 24 dots.
//
// Dot-phase mapping (2.7 B/MAC through L1):
//   lane = token (tau=2: lane owns tokens l and l+32)
//   warp = (row-group of 6 rows) x (channel half)   [8 warps]
//   x:  distinct LDS.128 per lane (writeback fully useful)
//   w:  uniform LDS.128 from SMEM-STAGED weights (R11 bug: these were LDG)
//   acc: 12 x u64 packed f32x2 per thread (row x token)
//
// Block: 64 tokens, 256 thr, grid 256, 3 CTAs/SM. Chunks of 64 channels;
// x (16 KB) and weights (6 KB) cp.async double-buffered together.
// ---------------------------------------------------------------------------

typedef unsigned long long u64;

__device__ __forceinline__ u64 fma2(u64 a, u64 b, u64 c) {
    u64 d;
    asm("fma.rn.f32x2 %0, %1, %2, %3;" : "=l"(d) : "l"(a), "l"(b), "l"(c));
    return d;
}
__device__ __forceinline__ u64 pk2(float lo, float hi) {
    u64 r;
    asm("mov.b64 %0, {%1, %2};" : "=l"(r) : "f"(lo), "f"(hi));
    return r;
}
__device__ __forceinline__ void upk2(u64 v, float& lo, float& hi) {
    asm("mov.b64 {%0, %1}, %2;" : "=f"(lo), "=f"(hi) : "l"(v));
}

// weights: g_WB[j4*24 + r] (float4 = row r's 4 channels at j4), 384 KB
static __device__ float4 g_WB[1024 * 24];

// ---------------------------------------------------------------------------
// prep: g_WB[j4*24 + r] = alpha_r * norm_w[j] * W_r[j],  j = j4*4 + c
// ---------------------------------------------------------------------------
__global__ void mhc_prep_kernel(const float* __restrict__ norm_w,
                                const float* __restrict__ W_pre,
                                const float* __restrict__ W_post,
                                const float* __restrict__ W_res,
                                const float* __restrict__ a_pre,
                                const float* __restrict__ a_post,
                                const float* __restrict__ a_res) {
    int idx = blockIdx.x * 256 + threadIdx.x;
    if (idx >= 1024 * 24) return;
    int j4 = idx / 24;
    int r  = idx - j4 * 24;
    float alpha;
    const float* Wrow;
    if (r < 4)       { alpha = a_pre[0];  Wrow = W_pre  + r * 4096; }
    else if (r < 8)  { alpha = a_post[0]; Wrow = W_post + (r - 4) * 4096; }
    else             { alpha = a_res[0];  Wrow = W_res  + (r - 8) * 4096; }
    int j = j4 * 4;
    float4 v;
    v.x = alpha * Wrow[j + 0] * norm_w[j + 0];
    v.y = alpha * Wrow[j + 1] * norm_w[j + 1];
    v.z = alpha * Wrow[j + 2] * norm_w[j + 2];
    v.w = alpha * Wrow[j + 3] * norm_w[j + 3];
    g_WB[idx] = v;
}

// Tile/loop config
#define TB       64      // tokens per block
#define NCHUNK   64      // chunks of 64 channels (16 j4)
#define CF4      16      // float4 per token per chunk
#define ROWB     272     // bytes per token row in x buffer (256 + 16 pad)
#define XBUFB    17408   // 64 * 272
#define WBUFB    6144    // 16 j4 * 24 rows * 16 B

// smem layout (bytes)
#define SMEM_SX    0          // 2 x-buffers                      34816
#define SMEM_SW    34816      // 2 w-buffers                      12288
#define SMEM_DOTS  47104      // float dots2[2][64][24]           12288
#define SMEM_SSQ   59392      // float ssqs[2][64]                  512
#define SMEM_SG    59904      // float sG[64][16]                  4096
#define SMEM_TOTAL 64000

__device__ __forceinline__ void load_chunk(uint32_t sbase, const float4* x4g,
                                           size_t tok0, int cc, int tid) {
    const int buf = cc & 1;
    // x: 1024 float4
#pragma unroll
    for (int i = 0; i < 4; i++) {
        int idx = i * 256 + tid;        // == tt*16 + c4
        int tt  = idx >> 4;
        int c4  = idx & 15;
        const float4* src = x4g + ((tok0 + tt) * 1024 + cc * CF4 + c4);
        uint32_t dst = sbase + SMEM_SX + buf * XBUFB + tt * ROWB + c4 * 16;
        asm volatile("cp.async.cg.shared.global [%0], [%1], 16;"
                     :: "r"(dst), "l"(src));
    }
    // weights: contiguous 384 float4 slab for this chunk
    {
        const float4* wsrc = g_WB + (size_t)cc * 16 * 24;
        uint32_t wdst = sbase + SMEM_SW + buf * WBUFB;
        asm volatile("cp.async.cg.shared.global [%0], [%1], 16;"
                     :: "r"(wdst + tid * 16), "l"(wsrc + tid));
        if (tid < 128) {
            asm volatile("cp.async.cg.shared.global [%0], [%1], 16;"
                         :: "r"(wdst + (256 + tid) * 16), "l"(wsrc + 256 + tid));
        }
    }
    asm volatile("cp.async.commit_group;");
}

__global__ void __launch_bounds__(256, 3)
mhc_main_kernel(const float* __restrict__ x,
                const float* __restrict__ b_pre,
                const float* __restrict__ b_post,
                const float* __restrict__ b_res,
                float* __restrict__ out) {
    extern __shared__ char smem[];
    float* dots2 = (float*)(smem + SMEM_DOTS);  // [2][64][24]
    float* ssqs  = (float*)(smem + SMEM_SSQ);   // [2][64]
    float* sG    = (float*)(smem + SMEM_SG);    // [64][16]

    const int tid  = threadIdx.x;
    const int w    = tid >> 5;
    const int lane = tid & 31;
    const int rg   = w & 3;   // row-group: rows 6*rg .. 6*rg+5
    const int h    = w >> 2;  // channel half
    const size_t tok0 = (size_t)blockIdx.x * TB;

    const float4*     x4g = (const float4*)x;
    const ulonglong2* xg2 = (const ulonglong2*)x;

    const uint32_t sbase = (uint32_t)__cvta_generic_to_shared(smem);

    u64 acc[12];
#pragma unroll
    for (int i = 0; i < 12; i++) acc[i] = 0ull;
    float sq0 = 0.0f, sq1 = 0.0f;  // rg==0 warps: ssq for tokens lane, lane+32

    // ------------------ Phase 1: double-buffered chunk loop -----------------
    load_chunk(sbase, x4g, tok0, 0, tid);

    for (int cc = 0; cc < NCHUNK; cc++) {
        if (cc < NCHUNK - 1) {
            load_chunk(sbase, x4g, tok0, cc + 1, tid);
            asm volatile("cp.async.wait_group 1;");
        } else {
            asm volatile("cp.async.wait_group 0;");
        }
        __syncthreads();

        const int buf = cc & 1;
        // x for lane's tokens, this warp's channel half (8 f4 per chunk)
        const char* xb0 = smem + SMEM_SX + buf * XBUFB + lane * ROWB + h * 128;
        const char* xb1 = xb0 + 32 * ROWB;
        // weights from smem: sw[(h*8 + m)*24 + rg*6 + r]
        const ulonglong2* wrow =
            (const ulonglong2*)(smem + SMEM_SW + buf * WBUFB) +
            ((h * 8) * 24 + rg * 6);

#pragma unroll
        for (int m = 0; m < 8; m++) {
            ulonglong2 xv0 = *(const ulonglong2*)(xb0 + m * 16);
            ulonglong2 xv1 = *(const ulonglong2*)(xb1 + m * 16);
            if (rg == 0) {
                float a, b;
                upk2(xv0.x, a, b); sq0 = fmaf(a, a, sq0); sq0 = fmaf(b, b, sq0);
                upk2(xv0.y, a, b); sq0 = fmaf(a, a, sq0); sq0 = fmaf(b, b, sq0);
                upk2(xv1.x, a, b); sq1 = fmaf(a, a, sq1); sq1 = fmaf(b, b, sq1);
                upk2(xv1.y, a, b); sq1 = fmaf(a, a, sq1); sq1 = fmaf(b, b, sq1);
            }
#pragma unroll
            for (int r = 0; r < 6; r++) {
                ulonglong2 wv = wrow[m * 24 + r];  // uniform LDS.128
                acc[r * 2 + 0] = fma2(wv.x, xv0.x, acc[r * 2 + 0]);
                acc[r * 2 + 0] = fma2(wv.y, xv0.y, acc[r * 2 + 0]);
                acc[r * 2 + 1] = fma2(wv.x, xv1.x, acc[r * 2 + 1]);
                acc[r * 2 + 1] = fma2(wv.y, xv1.y, acc[r * 2 + 1]);
            }
        }
        __syncthreads();  // all reads of this buffer done before reuse
    }

    // ------------------ Phase 2: write partial dots, reduce, Cayley ---------
#pragma unroll
    for (int r = 0; r < 6; r++) {
#pragma unroll
        for (int ti = 0; ti < 2; ti++) {
            float lo, hi;
            upk2(acc[r * 2 + ti], lo, hi);
            int t = lane + ti * 32;
            dots2[(h * TB + t) * 24 + rg * 6 + r] = lo + hi;
        }
    }
    if (rg == 0) {
        ssqs[h * TB + lane]      = sq0;
        ssqs[h * TB + lane + 32] = sq1;
    }
    __syncthreads();

    if (tid < TB) {
        const int t = tid;
        float ssq = ssqs[t] + ssqs[TB + t];
        float rinv = rsqrtf(ssq * (1.0f / 4096.0f) + 1e-6f);
        float d[24];
#pragma unroll
        for (int k = 0; k < 24; k++)
            d[k] = (dots2[t * 24 + k] + dots2[(TB + t) * 24 + k]) * rinv;

        float Hpre[4], Hpost[4];
#pragma unroll
        for (int i = 0; i < 4; i++) {
            Hpre[i]  = 1.0f / (1.0f + expf(-(d[i]     + b_pre[i])));
            Hpost[i] = 2.0f / (1.0f + expf(-(d[4 + i] + b_post[i])));
        }
        // Cayley: A = I - S, Bq = I + S, S = 0.5 (M - M^T)
        float A[4][4], Bq[4][4];
#pragma unroll
        for (int a = 0; a < 4; a++)
#pragma unroll
            for (int b = 0; b < 4; b++) {
                float Mab = d[8 + a * 4 + b] + b_res[a * 4 + b];
                float Mba = d[8 + b * 4 + a] + b_res[b * 4 + a];
                float S   = 0.5f * (Mab - Mba);
                float id  = (a == b) ? 1.0f : 0.0f;
                A[a][b]  = id - S;
                Bq[a][b] = id + S;
            }
#pragma unroll
        for (int r = 0; r < 4; r++) {
            float inv = 1.0f / A[r][r];
#pragma unroll
            for (int c = 0; c < 4; c++) { A[r][c] *= inv; Bq[r][c] *= inv; }
#pragma unroll
            for (int rr = 0; rr < 4; rr++) {
                if (rr == r) continue;
                float f = A[rr][r];
#pragma unroll
                for (int c = 0; c < 4; c++) {
                    A[rr][c]  -= f * A[r][c];
                    Bq[rr][c] -= f * Bq[r][c];
                }
            }
        }
#pragma unroll
        for (int m = 0; m < 4; m++)
#pragma unroll
            for (int n = 0; n < 4; n++)
                sG[t * 16 + m * 4 + n] = Bq[m][n] + Hpost[m] * Hpre[n];
    }
    __syncthreads();

    // ------------------ Phase 3: out = G @ x (per token, L2-hot x) ----------
    ulonglong2* og2 = (ulonglong2*)out;
    for (int it = 0; it < TB; it++) {
        u64 g2a[16];
#pragma unroll
        for (int q = 0; q < 16; q++) {
            float gv = sG[it * 16 + q];
            g2a[q] = pk2(gv, gv);
        }
        u64 xl[4], xh[4];
#pragma unroll
        for (int n = 0; n < 4; n++) {
            ulonglong2 v = xg2[(tok0 + it) * 1024 + n * 256 + tid];
            xl[n] = v.x;
            xh[n] = v.y;
        }
#pragma unroll
        for (int m = 0; m < 4; m++) {
            u64 al = 0ull, ah = 0ull;
#pragma unroll
            for (int n = 0; n < 4; n++) {
                al = fma2(g2a[m * 4 + n], xl[n], al);
                ah = fma2(g2a[m * 4 + n], xh[n], ah);
            }
            ulonglong2 o;
            o.x = al;
            o.y = ah;
            og2[(tok0 + it) * 1024 + m * 256 + tid] = o;
        }
    }
}

extern "C" void kernel_launch(void* const* d_in, const int* in_sizes, int n_in,
                              void* d_out, int out_size) {
    const float* x      = (const float*)d_in[0];
    const float* norm_w = (const float*)d_in[1];
    const float* W_pre  = (const float*)d_in[2];
    const float* W_post = (const float*)d_in[3];
    const float* W_res  = (const float*)d_in[4];
    const float* b_pre  = (const float*)d_in[5];
    const float* b_post = (const float*)d_in[6];
    const float* b_res  = (const float*)d_in[7];
    const float* a_pre  = (const float*)d_in[8];
    const float* a_post = (const float*)d_in[9];
    const float* a_res  = (const float*)d_in[10];
    float* out = (float*)d_out;

    const int BL   = in_sizes[0] / 4096;  // 16384 tokens
    const int nblk = BL / TB;             // 256 blocks

    cudaFuncSetAttribute(mhc_main_kernel,
                         cudaFuncAttributeMaxDynamicSharedMemorySize,
                         SMEM_TOTAL);

    mhc_prep_kernel<<<96, 256>>>(norm_w, W_pre, W_post, W_res,
                                 a_pre, a_post, a_res);
    mhc_main_kernel<<<nblk, 256, SMEM_TOTAL>>>(x, b_pre, b_post, b_res, out);
}

// round 13
// speedup vs baseline: 1.7018x; 1.0224x over previous
#include <cuda_runtime.h>
#include <cstdint>

// ---------------------------------------------------------------------------
// ManifoldHyperConnection, GB300 (sm_103a) — round 13: split-K + split-apply
//
//  prep: fold alpha/norm_w into g_WB[j4][row] (float4 of 4 channels).
//  K1  : grid 512 = 256 token-tiles x 2 channel-halves, 256 thr, 3 CTAs/SM.
//        Per block: 64 tokens x 2048 channels, 32 chunks of 64 ch,
//        cp.async double-buffered x (16KB) + weights (6KB).
//        lane = token (tau=2), warp = (row-group of 6) x (32-ch subhalf);
//        x distinct LDS.128, w uniform LDS.128, packed f32x2 accs.
//        Writes partial dots [64][24] + ssq per half to global scratch.
//  K2  : grid 2048, 8 tokens/CTA. Threads 0-7: sum partials, rms/sigmoid/
//        Cayley/fold -> sG. Then stream out = G @ x (packed FMA).
// ---------------------------------------------------------------------------

typedef unsigned long long u64;

__device__ __forceinline__ u64 fma2(u64 a, u64 b, u64 c) {
    u64 d;
    asm("fma.rn.f32x2 %0, %1, %2, %3;" : "=l"(d) : "l"(a), "l"(b), "l"(c));
    return d;
}
__device__ __forceinline__ u64 pk2(float lo, float hi) {
    u64 r;
    asm("mov.b64 %0, {%1, %2};" : "=l"(r) : "f"(lo), "f"(hi));
    return r;
}
__device__ __forceinline__ void upk2(u64 v, float& lo, float& hi) {
    asm("mov.b64 {%0, %1}, %2;" : "=f"(lo), "=f"(hi) : "l"(v));
}

// weights: g_WB[j4*24 + r] (float4 = row r's 4 channels at j4), 384 KB
static __device__ float4 g_WB[1024 * 24];
// split-K partials: [token][half][24] dots, [token][half] ssq
static __device__ float g_pd[16384 * 2 * 24];
static __device__ float g_pq[16384 * 2];

// ---------------------------------------------------------------------------
__global__ void mhc_prep_kernel(const float* __restrict__ norm_w,
                                const float* __restrict__ W_pre,
                                const float* __restrict__ W_post,
                                const float* __restrict__ W_res,
                                const float* __restrict__ a_pre,
                                const float* __restrict__ a_post,
                                const float* __restrict__ a_res) {
    int idx = blockIdx.x * 256 + threadIdx.x;
    if (idx >= 1024 * 24) return;
    int j4 = idx / 24;
    int r  = idx - j4 * 24;
    float alpha;
    const float* Wrow;
    if (r < 4)       { alpha = a_pre[0];  Wrow = W_pre  + r * 4096; }
    else if (r < 8)  { alpha = a_post[0]; Wrow = W_post + (r - 4) * 4096; }
    else             { alpha = a_res[0];  Wrow = W_res  + (r - 8) * 4096; }
    int j = j4 * 4;
    float4 v;
    v.x = alpha * Wrow[j + 0] * norm_w[j + 0];
    v.y = alpha * Wrow[j + 1] * norm_w[j + 1];
    v.z = alpha * Wrow[j + 2] * norm_w[j + 2];
    v.w = alpha * Wrow[j + 3] * norm_w[j + 3];
    g_WB[idx] = v;
}

// Tile/loop config (K1)
#define TB       64      // tokens per block
#define NCHUNK   32      // chunks of 64 channels per block (half the token)
#define CF4      16      // float4 per token per chunk
#define ROWB     272     // bytes per token row in x buffer (256 + 16 pad)
#define XBUFB    17408   // 64 * 272
#define WBUFB    6144    // 16 j4 * 24 rows * 16 B

// smem layout (K1, bytes)
#define SMEM_SX    0          // 2 x-buffers                      34816
#define SMEM_SW    34816      // 2 w-buffers                      12288
#define SMEM_DOTS  47104      // float dots2[2][64][24]           12288
#define SMEM_SSQ   59392      // float ssqs[2][64]                  512
#define SMEM_TOTAL 59904

__device__ __forceinline__ void load_chunk(uint32_t sbase, const float4* x4g,
                                           size_t tok0, int gc, int cc,
                                           int tid) {
    const int buf = cc & 1;
    // x: 1024 float4 (64 tokens x 16 f4)
#pragma unroll
    for (int i = 0; i < 4; i++) {
        int idx = i * 256 + tid;        // == tt*16 + c4
        int tt  = idx >> 4;
        int c4  = idx & 15;
        const float4* src = x4g + ((tok0 + tt) * 1024 + gc * CF4 + c4);
        uint32_t dst = sbase + SMEM_SX + buf * XBUFB + tt * ROWB + c4 * 16;
        asm volatile("cp.async.cg.shared.global [%0], [%1], 16;"
                     :: "r"(dst), "l"(src));
    }
    // weights: contiguous 384 float4 slab for this chunk
    {
        const float4* wsrc = g_WB + (size_t)gc * 16 * 24;
        uint32_t wdst = sbase + SMEM_SW + buf * WBUFB;
        asm volatile("cp.async.cg.shared.global [%0], [%1], 16;"
                     :: "r"(wdst + tid * 16), "l"(wsrc + tid));
        if (tid < 128) {
            asm volatile("cp.async.cg.shared.global [%0], [%1], 16;"
                         :: "r"(wdst + (256 + tid) * 16), "l"(wsrc + 256 + tid));
        }
    }
    asm volatile("cp.async.commit_group;");
}

// ---------------------------------------------------------------------------
// K1: split-K dot kernel. blockIdx.x = tile*2 + half.
// ---------------------------------------------------------------------------
__global__ void __launch_bounds__(256, 3)
mhc_dots_kernel(const float* __restrict__ x) {
    extern __shared__ char smem[];
    float* dots2 = (float*)(smem + SMEM_DOTS);  // [2][64][24]
    float* ssqs  = (float*)(smem + SMEM_SSQ);   // [2][64]

    const int tid  = threadIdx.x;
    const int w    = tid >> 5;
    const int lane = tid & 31;
    const int rg   = w & 3;   // row-group: rows 6*rg .. 6*rg+5
    const int h    = w >> 2;  // 32-ch subhalf within chunk
    const int tile = blockIdx.x >> 1;
    const int half = blockIdx.x & 1;
    const size_t tok0 = (size_t)tile * TB;

    const float4* x4g = (const float4*)x;
    const uint32_t sbase = (uint32_t)__cvta_generic_to_shared(smem);

    u64 acc[12];
#pragma unroll
    for (int i = 0; i < 12; i++) acc[i] = 0ull;
    float sq0 = 0.0f, sq1 = 0.0f;

    // ------------------ double-buffered chunk loop --------------------------
    load_chunk(sbase, x4g, tok0, half * NCHUNK, 0, tid);

    for (int cc = 0; cc < NCHUNK; cc++) {
        if (cc < NCHUNK - 1) {
            load_chunk(sbase, x4g, tok0, half * NCHUNK + cc + 1, cc + 1, tid);
            asm volatile("cp.async.wait_group 1;");
        } else {
            asm volatile("cp.async.wait_group 0;");
        }
        __syncthreads();

        const int buf = cc & 1;
        const char* xb0 = smem + SMEM_SX + buf * XBUFB + lane * ROWB + h * 128;
        const char* xb1 = xb0 + 32 * ROWB;
        const ulonglong2* wrow =
            (const ulonglong2*)(smem + SMEM_SW + buf * WBUFB) +
            ((h * 8) * 24 + rg * 6);

#pragma unroll
        for (int m = 0; m < 8; m++) {
            ulonglong2 xv0 = *(const ulonglong2*)(xb0 + m * 16);
            ulonglong2 xv1 = *(const ulonglong2*)(xb1 + m * 16);
            if (rg == 0) {
                float a, b;
                upk2(xv0.x, a, b); sq0 = fmaf(a, a, sq0); sq0 = fmaf(b, b, sq0);
                upk2(xv0.y, a, b); sq0 = fmaf(a, a, sq0); sq0 = fmaf(b, b, sq0);
                upk2(xv1.x, a, b); sq1 = fmaf(a, a, sq1); sq1 = fmaf(b, b, sq1);
                upk2(xv1.y, a, b); sq1 = fmaf(a, a, sq1); sq1 = fmaf(b, b, sq1);
            }
#pragma unroll
            for (int r = 0; r < 6; r++) {
                ulonglong2 wv = wrow[m * 24 + r];  // uniform LDS.128
                acc[r * 2 + 0] = fma2(wv.x, xv0.x, acc[r * 2 + 0]);
                acc[r * 2 + 0] = fma2(wv.y, xv0.y, acc[r * 2 + 0]);
                acc[r * 2 + 1] = fma2(wv.x, xv1.x, acc[r * 2 + 1]);
                acc[r * 2 + 1] = fma2(wv.y, xv1.y, acc[r * 2 + 1]);
            }
        }
        __syncthreads();  // all reads of this buffer done before reuse
    }

    // ------------------ combine subhalves, write global partials ------------
#pragma unroll
    for (int r = 0; r < 6; r++) {
#pragma unroll
        for (int ti = 0; ti < 2; ti++) {
            float lo, hi;
            upk2(acc[r * 2 + ti], lo, hi);
            int t = lane + ti * 32;
            dots2[(h * TB + t) * 24 + rg * 6 + r] = lo + hi;
        }
    }
    if (rg == 0) {
        ssqs[h * TB + lane]      = sq0;
        ssqs[h * TB + lane + 32] = sq1;
    }
    __syncthreads();

    for (int idx = tid; idx < TB * 24; idx += 256) {
        int t = idx / 24;
        int k = idx - t * 24;
        float s = dots2[t * 24 + k] + dots2[(TB + t) * 24 + k];
        g_pd[((tok0 + t) * 2 + half) * 24 + k] = s;
    }
    if (tid < TB) {
        g_pq[(tok0 + tid) * 2 + half] = ssqs[tid] + ssqs[TB + tid];
    }
}

// ---------------------------------------------------------------------------
// K2: apply kernel. 8 tokens/block, grid 2048.
// ---------------------------------------------------------------------------
__global__ void __launch_bounds__(256)
mhc_apply_kernel(const float* __restrict__ x,
                 const float* __restrict__ b_pre,
                 const float* __restrict__ b_post,
                 const float* __restrict__ b_res,
                 float* __restrict__ out) {
    __shared__ float sG[8 * 16];
    const int tid = threadIdx.x;
    const size_t tok0 = (size_t)blockIdx.x * 8;

    if (tid < 8) {
        const size_t t = tok0 + tid;
        float ssq = g_pq[t * 2] + g_pq[t * 2 + 1];
        float rinv = rsqrtf(ssq * (1.0f / 4096.0f) + 1e-6f);
        float d[24];
#pragma unroll
        for (int k = 0; k < 24; k++)
            d[k] = (g_pd[t * 48 + k] + g_pd[t * 48 + 24 + k]) * rinv;

        float Hpre[4], Hpost[4];
#pragma unroll
        for (int i = 0; i < 4; i++) {
            Hpre[i]  = 1.0f / (1.0f + expf(-(d[i]     + b_pre[i])));
            Hpost[i] = 2.0f / (1.0f + expf(-(d[4 + i] + b_post[i])));
        }
        // Cayley: A = I - S, Bq = I + S, S = 0.5 (M - M^T)
        float A[4][4], Bq[4][4];
#pragma unroll
        for (int a = 0; a < 4; a++)
#pragma unroll
            for (int b = 0; b < 4; b++) {
                float Mab = d[8 + a * 4 + b] + b_res[a * 4 + b];
                float Mba = d[8 + b * 4 + a] + b_res[b * 4 + a];
                float S   = 0.5f * (Mab - Mba);
                float id  = (a == b) ? 1.0f : 0.0f;
                A[a][b]  = id - S;
                Bq[a][b] = id + S;
            }
#pragma unroll
        for (int r = 0; r < 4; r++) {
            float inv = 1.0f / A[r][r];
#pragma unroll
            for (int c = 0; c < 4; c++) { A[r][c] *= inv; Bq[r][c] *= inv; }
#pragma unroll
            for (int rr = 0; rr < 4; rr++) {
                if (rr == r) continue;
                float f = A[rr][r];
#pragma unroll
                for (int c = 0; c < 4; c++) {
                    A[rr][c]  -= f * A[r][c];
                    Bq[rr][c] -= f * Bq[r][c];
                }
            }
        }
#pragma unroll
        for (int m = 0; m < 4; m++)
#pragma unroll
            for (int n = 0; n < 4; n++)
                sG[tid * 16 + m * 4 + n] = Bq[m][n] + Hpost[m] * Hpre[n];
    }
    __syncthreads();

    const ulonglong2* xg2 = (const ulonglong2*)x;
    ulonglong2*       og2 = (ulonglong2*)out;
    for (int it = 0; it < 8; it++) {
        u64 g2a[16];
#pragma unroll
        for (int q = 0; q < 16; q++) {
            float gv = sG[it * 16 + q];
            g2a[q] = pk2(gv, gv);
        }
        u64 xl[4], xh[4];
#pragma unroll
        for (int n = 0; n < 4; n++) {
            ulonglong2 v = xg2[(tok0 + it) * 1024 + n * 256 + tid];
            xl[n] = v.x;
            xh[n] = v.y;
        }
#pragma unroll
        for (int m = 0; m < 4; m++) {
            u64 al = 0ull, ah = 0ull;
#pragma unroll
            for (int n = 0; n < 4; n++) {
                al = fma2(g2a[m * 4 + n], xl[n], al);
                ah = fma2(g2a[m * 4 + n], xh[n], ah);
            }
            ulonglong2 o;
            o.x = al;
            o.y = ah;
            og2[(tok0 + it) * 1024 + m * 256 + tid] = o;
        }
    }
}

extern "C" void kernel_launch(void* const* d_in, const int* in_sizes, int n_in,
                              void* d_out, int out_size) {
    const float* x      = (const float*)d_in[0];
    const float* norm_w = (const float*)d_in[1];
    const float* W_pre  = (const float*)d_in[2];
    const float* W_post = (const float*)d_in[3];
    const float* W_res  = (const float*)d_in[4];
    const float* b_pre  = (const float*)d_in[5];
    const float* b_post = (const float*)d_in[6];
    const float* b_res  = (const float*)d_in[7];
    const float* a_pre  = (const float*)d_in[8];
    const float* a_post = (const float*)d_in[9];
    const float* a_res  = (const float*)d_in[10];
    float* out = (float*)d_out;

    const int BL = in_sizes[0] / 4096;  // 16384 tokens

    cudaFuncSetAttribute(mhc_dots_kernel,
                         cudaFuncAttributeMaxDynamicSharedMemorySize,
                         SMEM_TOTAL);

    mhc_prep_kernel<<<96, 256>>>(norm_w, W_pre, W_post, W_res,
                                 a_pre, a_post, a_res);
    mhc_dots_kernel<<<(BL / TB) * 2, 256, SMEM_TOTAL>>>(x);
    mhc_apply_kernel<<<BL / 8, 256>>>(x, b_pre, b_post, b_res, out);
}

// round 14
// speedup vs baseline: 1.8049x; 1.0606x over previous
#include <cuda_runtime.h>
#include <cstdint>

// ---------------------------------------------------------------------------
// ManifoldHyperConnection, GB300 (sm_103a) — round 14: split-K=4
//
//  prep: fold alpha/norm_w into g_WB[j4][row] (float4 of 4 channels).
//  K1  : grid 1024 = 256 token-tiles x 4 channel-quarters, 256 thr, 3 CTAs/SM.
//        Per block: 64 tokens x 1024 channels, 16 chunks of 64 ch,
//        cp.async double-buffered x (16KB) + weights (6KB).
//        lane = token (tau=2), warp = (row-group of 6) x (32-ch subhalf);
//        x distinct LDS.128, w uniform LDS.128, packed f32x2 accs.
//        Partial dots [64][24] + ssq per quarter -> global scratch.
//        (dots staging smem aliased into dead x buffers: SMEM_TOTAL 47.1 KB)
//  K2  : grid 2048, 8 tokens/CTA. Threads 0-7: sum 4 partials, rms/sigmoid/
//        Cayley/fold -> sG. Then stream out = G @ x (packed FMA).
// ---------------------------------------------------------------------------

typedef unsigned long long u64;

__device__ __forceinline__ u64 fma2(u64 a, u64 b, u64 c) {
    u64 d;
    asm("fma.rn.f32x2 %0, %1, %2, %3;" : "=l"(d) : "l"(a), "l"(b), "l"(c));
    return d;
}
__device__ __forceinline__ u64 pk2(float lo, float hi) {
    u64 r;
    asm("mov.b64 %0, {%1, %2};" : "=l"(r) : "f"(lo), "f"(hi));
    return r;
}
__device__ __forceinline__ void upk2(u64 v, float& lo, float& hi) {
    asm("mov.b64 {%0, %1}, %2;" : "=f"(lo), "=f"(hi) : "l"(v));
}

// weights: g_WB[j4*24 + r] (float4 = row r's 4 channels at j4), 384 KB
static __device__ float4 g_WB[1024 * 24];
// split-K partials: [token][quarter][24] dots, [token][quarter] ssq
static __device__ float g_pd[16384 * 4 * 24];
static __device__ float g_pq[16384 * 4];

// ---------------------------------------------------------------------------
__global__ void mhc_prep_kernel(const float* __restrict__ norm_w,
                                const float* __restrict__ W_pre,
                                const float* __restrict__ W_post,
                                const float* __restrict__ W_res,
                                const float* __restrict__ a_pre,
                                const float* __restrict__ a_post,
                                const float* __restrict__ a_res) {
    int idx = blockIdx.x * 256 + threadIdx.x;
    if (idx >= 1024 * 24) return;
    int j4 = idx / 24;
    int r  = idx - j4 * 24;
    float alpha;
    const float* Wrow;
    if (r < 4)       { alpha = a_pre[0];  Wrow = W_pre  + r * 4096; }
    else if (r < 8)  { alpha = a_post[0]; Wrow = W_post + (r - 4) * 4096; }
    else             { alpha = a_res[0];  Wrow = W_res  + (r - 8) * 4096; }
    int j = j4 * 4;
    float4 v;
    v.x = alpha * Wrow[j + 0] * norm_w[j + 0];
    v.y = alpha * Wrow[j + 1] * norm_w[j + 1];
    v.z = alpha * Wrow[j + 2] * norm_w[j + 2];
    v.w = alpha * Wrow[j + 3] * norm_w[j + 3];
    g_WB[idx] = v;
}

// Tile/loop config (K1)
#define TB       64      // tokens per block
#define NSPLIT   4       // channel quarters
#define NCHUNK   16      // chunks of 64 channels per block (quarter token)
#define CF4      16      // float4 per token per chunk
#define ROWB     272     // bytes per token row in x buffer (256 + 16 pad)
#define XBUFB    17408   // 64 * 272
#define WBUFB    6144    // 16 j4 * 24 rows * 16 B

// smem layout (K1, bytes). dots/ssq staging ALIASES the x buffers (dead
// after the mainloop's final __syncthreads).
#define SMEM_SX    0          // 2 x-buffers                      34816
#define SMEM_SW    34816      // 2 w-buffers                      12288
#define SMEM_DOTS  0          // float dots2[2][64][24]   (alias) 12288
#define SMEM_SSQ   12288      // float ssqs[2][64]        (alias)   512
#define SMEM_TOTAL 47104

__device__ __forceinline__ void load_chunk(uint32_t sbase, const float4* x4g,
                                           size_t tok0, int gc, int cc,
                                           int tid) {
    const int buf = cc & 1;
    // x: 1024 float4 (64 tokens x 16 f4)
#pragma unroll
    for (int i = 0; i < 4; i++) {
        int idx = i * 256 + tid;        // == tt*16 + c4
        int tt  = idx >> 4;
        int c4  = idx & 15;
        const float4* src = x4g + ((tok0 + tt) * 1024 + gc * CF4 + c4);
        uint32_t dst = sbase + SMEM_SX + buf * XBUFB + tt * ROWB + c4 * 16;
        asm volatile("cp.async.cg.shared.global [%0], [%1], 16;"
                     :: "r"(dst), "l"(src));
    }
    // weights: contiguous 384 float4 slab for this chunk
    {
        const float4* wsrc = g_WB + (size_t)gc * 16 * 24;
        uint32_t wdst = sbase + SMEM_SW + buf * WBUFB;
        asm volatile("cp.async.cg.shared.global [%0], [%1], 16;"
                     :: "r"(wdst + tid * 16), "l"(wsrc + tid));
        if (tid < 128) {
            asm volatile("cp.async.cg.shared.global [%0], [%1], 16;"
                         :: "r"(wdst + (256 + tid) * 16), "l"(wsrc + 256 + tid));
        }
    }
    asm volatile("cp.async.commit_group;");
}

// ---------------------------------------------------------------------------
// K1: split-K dot kernel. blockIdx.x = tile*4 + quarter.
// ---------------------------------------------------------------------------
__global__ void __launch_bounds__(256, 3)
mhc_dots_kernel(const float* __restrict__ x) {
    extern __shared__ char smem[];
    float* dots2 = (float*)(smem + SMEM_DOTS);  // [2][64][24] (aliased)
    float* ssqs  = (float*)(smem + SMEM_SSQ);   // [2][64]     (aliased)

    const int tid  = threadIdx.x;
    const int w    = tid >> 5;
    const int lane = tid & 31;
    const int rg   = w & 3;   // row-group: rows 6*rg .. 6*rg+5
    const int h    = w >> 2;  // 32-ch subhalf within chunk
    const int tile = blockIdx.x >> 2;
    const int qrt  = blockIdx.x & 3;
    const size_t tok0 = (size_t)tile * TB;

    const float4* x4g = (const float4*)x;
    const uint32_t sbase = (uint32_t)__cvta_generic_to_shared(smem);

    u64 acc[12];
#pragma unroll
    for (int i = 0; i < 12; i++) acc[i] = 0ull;
    float sq0 = 0.0f, sq1 = 0.0f;

    // ------------------ double-buffered chunk loop --------------------------
    load_chunk(sbase, x4g, tok0, qrt * NCHUNK, 0, tid);

    for (int cc = 0; cc < NCHUNK; cc++) {
        if (cc < NCHUNK - 1) {
            load_chunk(sbase, x4g, tok0, qrt * NCHUNK + cc + 1, cc + 1, tid);
            asm volatile("cp.async.wait_group 1;");
        } else {
            asm volatile("cp.async.wait_group 0;");
        }
        __syncthreads();

        const int buf = cc & 1;
        const char* xb0 = smem + SMEM_SX + buf * XBUFB + lane * ROWB + h * 128;
        const char* xb1 = xb0 + 32 * ROWB;
        const ulonglong2* wrow =
            (const ulonglong2*)(smem + SMEM_SW + buf * WBUFB) +
            ((h * 8) * 24 + rg * 6);

#pragma unroll
        for (int m = 0; m < 8; m++) {
            ulonglong2 xv0 = *(const ulonglong2*)(xb0 + m * 16);
            ulonglong2 xv1 = *(const ulonglong2*)(xb1 + m * 16);
            if (rg == 0) {
                float a, b;
                upk2(xv0.x, a, b); sq0 = fmaf(a, a, sq0); sq0 = fmaf(b, b, sq0);
                upk2(xv0.y, a, b); sq0 = fmaf(a, a, sq0); sq0 = fmaf(b, b, sq0);
                upk2(xv1.x, a, b); sq1 = fmaf(a, a, sq1); sq1 = fmaf(b, b, sq1);
                upk2(xv1.y, a, b); sq1 = fmaf(a, a, sq1); sq1 = fmaf(b, b, sq1);
            }
#pragma unroll
            for (int r = 0; r < 6; r++) {
                ulonglong2 wv = wrow[m * 24 + r];  // uniform LDS.128
                acc[r * 2 + 0] = fma2(wv.x, xv0.x, acc[r * 2 + 0]);
                acc[r * 2 + 0] = fma2(wv.y, xv0.y, acc[r * 2 + 0]);
                acc[r * 2 + 1] = fma2(wv.x, xv1.x, acc[r * 2 + 1]);
                acc[r * 2 + 1] = fma2(wv.y, xv1.y, acc[r * 2 + 1]);
            }
        }
        __syncthreads();  // all reads of this buffer done before reuse
    }

    // ------------------ combine subhalves, write global partials ------------
    // (dots2/ssqs alias the x buffers; mainloop reads are fenced by the
    //  loop-end __syncthreads above)
#pragma unroll
    for (int r = 0; r < 6; r++) {
#pragma unroll
        for (int ti = 0; ti < 2; ti++) {
            float lo, hi;
            upk2(acc[r * 2 + ti], lo, hi);
            int t = lane + ti * 32;
            dots2[(h * TB + t) * 24 + rg * 6 + r] = lo + hi;
        }
    }
    if (rg == 0) {
        ssqs[h * TB + lane]      = sq0;
        ssqs[h * TB + lane + 32] = sq1;
    }
    __syncthreads();

    for (int idx = tid; idx < TB * 24; idx += 256) {
        int t = idx / 24;
        int k = idx - t * 24;
        float s = dots2[t * 24 + k] + dots2[(TB + t) * 24 + k];
        g_pd[((tok0 + t) * NSPLIT + qrt) * 24 + k] = s;
    }
    if (tid < TB) {
        g_pq[(tok0 + tid) * NSPLIT + qrt] = ssqs[tid] + ssqs[TB + tid];
    }
}

// ---------------------------------------------------------------------------
// K2: apply kernel. 8 tokens/block, grid 2048.
// ---------------------------------------------------------------------------
__global__ void __launch_bounds__(256)
mhc_apply_kernel(const float* __restrict__ x,
                 const float* __restrict__ b_pre,
                 const float* __restrict__ b_post,
                 const float* __restrict__ b_res,
                 float* __restrict__ out) {
    __shared__ float sG[8 * 16];
    const int tid = threadIdx.x;
    const size_t tok0 = (size_t)blockIdx.x * 8;

    if (tid < 8) {
        const size_t t = tok0 + tid;
        float ssq = g_pq[t * 4] + g_pq[t * 4 + 1] + g_pq[t * 4 + 2]
                  + g_pq[t * 4 + 3];
        float rinv = rsqrtf(ssq * (1.0f / 4096.0f) + 1e-6f);
        float d[24];
#pragma unroll
        for (int k = 0; k < 24; k++)
            d[k] = (g_pd[t * 96 + k]      + g_pd[t * 96 + 24 + k]
                  + g_pd[t * 96 + 48 + k] + g_pd[t * 96 + 72 + k]) * rinv;

        float Hpre[4], Hpost[4];
#pragma unroll
        for (int i = 0; i < 4; i++) {
            Hpre[i]  = 1.0f / (1.0f + expf(-(d[i]     + b_pre[i])));
            Hpost[i] = 2.0f / (1.0f + expf(-(d[4 + i] + b_post[i])));
        }
        // Cayley: A = I - S, Bq = I + S, S = 0.5 (M - M^T)
        float A[4][4], Bq[4][4];
#pragma unroll
        for (int a = 0; a < 4; a++)
#pragma unroll
            for (int b = 0; b < 4; b++) {
                float Mab = d[8 + a * 4 + b] + b_res[a * 4 + b];
                float Mba = d[8 + b * 4 + a] + b_res[b * 4 + a];
                float S   = 0.5f * (Mab - Mba);
                float id  = (a == b) ? 1.0f : 0.0f;
                A[a][b]  = id - S;
                Bq[a][b] = id + S;
            }
#pragma unroll
        for (int r = 0; r < 4; r++) {
            float inv = 1.0f / A[r][r];
#pragma unroll
            for (int c = 0; c < 4; c++) { A[r][c] *= inv; Bq[r][c] *= inv; }
#pragma unroll
            for (int rr = 0; rr < 4; rr++) {
                if (rr == r) continue;
                float f = A[rr][r];
#pragma unroll
                for (int c = 0; c < 4; c++) {
                    A[rr][c]  -= f * A[r][c];
                    Bq[rr][c] -= f * Bq[r][c];
                }
            }
        }
#pragma unroll
        for (int m = 0; m < 4; m++)
#pragma unroll
            for (int n = 0; n < 4; n++)
                sG[tid * 16 + m * 4 + n] = Bq[m][n] + Hpost[m] * Hpre[n];
    }
    __syncthreads();

    const ulonglong2* xg2 = (const ulonglong2*)x;
    ulonglong2*       og2 = (ulonglong2*)out;
    for (int it = 0; it < 8; it++) {
        u64 g2a[16];
#pragma unroll
        for (int q = 0; q < 16; q++) {
            float gv = sG[it * 16 + q];
            g2a[q] = pk2(gv, gv);
        }
        u64 xl[4], xh[4];
#pragma unroll
        for (int n = 0; n < 4; n++) {
            ulonglong2 v = xg2[(tok0 + it) * 1024 + n * 256 + tid];
            xl[n] = v.x;
            xh[n] = v.y;
        }
#pragma unroll
        for (int m = 0; m < 4; m++) {
            u64 al = 0ull, ah = 0ull;
#pragma unroll
            for (int n = 0; n < 4; n++) {
                al = fma2(g2a[m * 4 + n], xl[n], al);
                ah = fma2(g2a[m * 4 + n], xh[n], ah);
            }
            ulonglong2 o;
            o.x = al;
            o.y = ah;
            og2[(tok0 + it) * 1024 + m * 256 + tid] = o;
        }
    }
}

extern "C" void kernel_launch(void* const* d_in, const int* in_sizes, int n_in,
                              void* d_out, int out_size) {
    const float* x      = (const float*)d_in[0];
    const float* norm_w = (const float*)d_in[1];
    const float* W_pre  = (const float*)d_in[2];
    const float* W_post = (const float*)d_in[3];
    const float* W_res  = (const float*)d_in[4];
    const float* b_pre  = (const float*)d_in[5];
    const float* b_post = (const float*)d_in[6];
    const float* b_res  = (const float*)d_in[7];
    const float* a_pre  = (const float*)d_in[8];
    const float* a_post = (const float*)d_in[9];
    const float* a_res  = (const float*)d_in[10];
    float* out = (float*)d_out;

    const int BL = in_sizes[0] / 4096;  // 16384 tokens

    cudaFuncSetAttribute(mhc_dots_kernel,
                         cudaFuncAttributeMaxDynamicSharedMemorySize,
                         SMEM_TOTAL);

    mhc_prep_kernel<<<96, 256>>>(norm_w, W_pre, W_post, W_res,
                                 a_pre, a_post, a_res);
    mhc_dots_kernel<<<(BL / TB) * NSPLIT, 256, SMEM_TOTAL>>>(x);
    mhc_apply_kernel<<<BL / 8, 256>>>(x, b_pre, b_post, b_res, out);
}